// round 10
// baseline (speedup 1.0000x reference)
#include <cuda_runtime.h>
#include <cuda_fp16.h>
#include <cstdint>

#define BB 16
#define TT 1024
#define HH 256
#define LL 2048
#define MQ 64
#define TCHK 32
#define NCHUNK 32
#define NTHR 256

// smem pitches (halves); stride % 64 == 8 -> conflict-free ldsm
#define QP 264
#define XP 264
#define EP 1032
#define XCHB (TCHK * XP * 2)      // 16896 B per X buffer

// smem byte offsets
#define SO_RS   0                          // float rs[2][64]
#define SO_INV  512                        // float inv[64]
#define SO_FLAG 768
#define SO_Q    1024                       // 64*264*2 = 33792
#define SO_X0   (SO_Q + 33792)             // 2 X buffers
#define SO_ES   (SO_X0 + 2 * XCHB)         // 64*1032*2 = 132096
#define SMEM_BYTES (SO_ES + MQ * EP * 2)   // 200704 B

__device__ __half g_Xh[(size_t)BB * TT * HH];

__device__ __forceinline__ uint32_t smem_u32(const void* p) {
    uint32_t a;
    asm("{ .reg .u64 t; cvta.to.shared.u64 t, %1; cvt.u32.u64 %0, t; }" : "=r"(a) : "l"(p));
    return a;
}
__device__ __forceinline__ void ldsm4(uint32_t a, uint32_t* r) {
    asm volatile("ldmatrix.sync.aligned.m8n8.x4.shared.b16 {%0,%1,%2,%3}, [%4];"
                 : "=r"(r[0]), "=r"(r[1]), "=r"(r[2]), "=r"(r[3]) : "r"(a));
}
__device__ __forceinline__ void ldsm4t(uint32_t a, uint32_t* r) {
    asm volatile("ldmatrix.sync.aligned.m8n8.x4.trans.shared.b16 {%0,%1,%2,%3}, [%4];"
                 : "=r"(r[0]), "=r"(r[1]), "=r"(r[2]), "=r"(r[3]) : "r"(a));
}
__device__ __forceinline__ void mma16816(float* d, const uint32_t* a, const uint32_t* b) {
    asm volatile("mma.sync.aligned.m16n8k16.row.col.f32.f16.f16.f32 "
                 "{%0,%1,%2,%3}, {%4,%5,%6,%7}, {%8,%9}, {%0,%1,%2,%3};"
                 : "+f"(d[0]), "+f"(d[1]), "+f"(d[2]), "+f"(d[3])
                 : "r"(a[0]), "r"(a[1]), "r"(a[2]), "r"(a[3]), "r"(b[0]), "r"(b[1]));
}
__device__ __forceinline__ void cpasync16(uint32_t sa, const void* ga) {
    asm volatile("cp.async.ca.shared.global [%0], [%1], 16;" :: "r"(sa), "l"(ga));
}
#define CP_COMMIT()  asm volatile("cp.async.commit_group;" ::: "memory")
#define CP_WAIT0()   asm volatile("cp.async.wait_group 0;" ::: "memory")

// ---------------- X f32 -> fp16 convert ----------------
__global__ void __launch_bounds__(256)
xconv(const float* __restrict__ X)
{
    const size_t i = ((size_t)blockIdx.x * 256 + threadIdx.x) * 8;
    float4 a = *(const float4*)(X + i);
    float4 b = *(const float4*)(X + i + 4);
    half2 h[4] = { __floats2half2_rn(a.x, a.y), __floats2half2_rn(a.z, a.w),
                   __floats2half2_rn(b.x, b.y), __floats2half2_rn(b.z, b.w) };
    *(uint4*)(g_Xh + i) = *(uint4*)h;
}

// ---- main fused kernel: 256 threads, 4M x 2N warps, Q register-resident ----
__global__ void __launch_bounds__(NTHR, 1)
pla_mma(const void*  __restrict__ labels_raw, // (B,L) int32/int64
        const float* __restrict__ table,      // (C+1,H)
        float* __restrict__ logits,           // (B,L,H)
        float* __restrict__ att)              // (B,L,T)
{
    extern __shared__ char sm[];
    float*  rs  = (float*)(sm + SO_RS);
    float*  inv = (float*)(sm + SO_INV);
    __half* Qs  = (__half*)(sm + SO_Q);
    __half* Es  = (__half*)(sm + SO_ES);
    const uint32_t smb = smem_u32(sm);
    const uint32_t Qb = smb + SO_Q, Xb0 = smb + SO_X0, EsB = smb + SO_ES;

    const int tid = threadIdx.x, lane = tid & 31, w = tid >> 5;
    const int wm = w & 3, wn = w >> 2;       // 4(M) x 2(N)
    const int m0 = wm * 16;
    const int b = blockIdx.x >> 5, lt = blockIdx.x & 31, l0 = lt * MQ;
    const size_t bL = (size_t)b * LL;
    const __half* Xg = g_Xh + (size_t)b * TT * HH;

    // cp.async geometry: 8 threads/row, 4 x 16B each (512B data per row)
    const int xr = tid >> 3, xc = (tid & 7) * 32;
    const uint32_t xdst = (uint32_t)((xr * XP + xc) * 2);

    // ---- prime X[0] (overlaps flag + Q gather) ----
    {
        const __half* src = Xg + (size_t)xr * HH + xc;
        #pragma unroll
        for (int j = 0; j < 4; j++)
            cpasync16(Xb0 + xdst + j * 16, src + j * 8);
        CP_COMMIT();
    }

    // labels dtype detection (int64 LE, values < 2^31 => odd words zero)
    int* flag = (int*)(sm + SO_FLAG);
    if (tid == 0) {
        const int* li = (const int*)labels_raw;
        *flag = ((li[1] | li[3] | li[5] | li[7] | li[9] | li[11] | li[13] | li[15]) == 0);
    }
    __syncthreads();
    const bool is64 = (*flag != 0);

    // ---- gather Q (table[labels]) -> fp16 smem ----
    {
        const int q = tid >> 2, c0 = (tid & 3) * 4;
        const long long lidx = (long long)b * LL + l0 + q;
        const long long lab = is64 ? ((const long long*)labels_raw)[lidx]
                                   : (long long)((const int*)labels_raw)[lidx];
        const float* row = table + (size_t)lab * HH;
        #pragma unroll
        for (int j = 0; j < 16; j++) {
            const int col = c0 + j * 16;
            float4 v = *(const float4*)(row + col);
            *(half2*)(Qs + q * QP + col)     = __floats2half2_rn(v.x, v.y);
            *(half2*)(Qs + q * QP + col + 2) = __floats2half2_rn(v.z, v.w);
        }
    }
    __syncthreads();   // Qs visible to all warps

    // ---- Q fragments: register-resident for the whole kernel (64 regs) ----
    // M=16/warp -> one A fragment (4 regs) per k-step, 16 k-steps.
    uint32_t Aq[64];
    {
        const uint32_t a1_0 = Qb + (uint32_t)(((m0 + (lane & 15)) * QP
                                               + ((lane >> 4) << 3)) * 2);
        #pragma unroll
        for (int k = 0; k < 16; k++) ldsm4(a1_0 + k * 32, Aq + 4 * k);
    }

    float rsum0 = 0.f, rsum1 = 0.f;   // rows m0+r, m0+8+r (partial over wn's t-slice)
    float o[64];
    #pragma unroll
    for (int i = 0; i < 64; i++) o[i] = 0.f;

    // MMA1 B (X, K-major, 16t x 16k per ldsm4): t-rows wn*16..+15
    const uint32_t b1r = (uint32_t)(((wn * 16 + (lane & 7) + ((lane >> 4) << 3)) * XP
                                     + ((lane >> 3) & 1) * 8) * 2);
    // MMA2 A (Es rows m0..m0+15)
    const uint32_t a2r = EsB + (uint32_t)(((m0 + (lane & 15)) * EP
                                           + ((lane >> 4) << 3)) * 2);
    // MMA2 B (X, MN-major via trans ldsm): h-slice wn*128..+127
    const uint32_t b2r = (uint32_t)(((lane & 15) * XP + wn * 128
                                     + ((lane >> 4) << 3)) * 2);

    const int r = lane >> 2, c2 = (lane & 3) * 2;

    #pragma unroll 1
    for (int i = 0; i < NCHUNK; i++) {
        const uint32_t xcur = Xb0 + (uint32_t)(i & 1) * XCHB;

        CP_WAIT0();          // X[i] landed
        __syncthreads();     // X[i] visible; MMA2(i-1) readers of X[i-1] drained

        // issue X[i+1] into the other slot (held X[i-1]; its readers are done)
        if (i + 1 < NCHUNK) {
            const uint32_t xn = Xb0 + (uint32_t)((i + 1) & 1) * XCHB;
            const __half* src = Xg + (size_t)((i + 1) * TCHK + xr) * HH + xc;
            #pragma unroll
            for (int j = 0; j < 4; j++)
                cpasync16(xn + xdst + j * 16, src + j * 8);
        }
        CP_COMMIT();

        // ---- MMA1: S[16q x 16t per warp] = Q * Xchunk^T (K=256) ----
        float sa0[4] = {0.f, 0.f, 0.f, 0.f};
        float sa1[4] = {0.f, 0.f, 0.f, 0.f};
        #pragma unroll
        for (int k = 0; k < 16; k++) {
            uint32_t Bv[4];
            ldsm4(xcur + b1r + k * 32, Bv);
            mma16816(sa0, Aq + 4 * k, Bv);
            mma16816(sa1, Aq + 4 * k, Bv + 2);
        }

        // ---- epilogue: e = exp(s) -> Es monolith + running row sums ----
        {
            const float e0 = __expf(sa0[0]), e1 = __expf(sa0[1]);
            const float e2 = __expf(sa0[2]), e3 = __expf(sa0[3]);
            const float f0 = __expf(sa1[0]), f1 = __expf(sa1[1]);
            const float f2 = __expf(sa1[2]), f3 = __expf(sa1[3]);
            rsum0 += e0 + e1 + f0 + f1;
            rsum1 += e2 + e3 + f2 + f3;
            __half* e_lo = Es + (m0 + r) * EP + i * TCHK + wn * 16 + c2;
            __half* e_hi = e_lo + 8 * EP;
            *(half2*)(e_lo)     = __floats2half2_rn(e0, e1);
            *(half2*)(e_lo + 8) = __floats2half2_rn(f0, f1);
            *(half2*)(e_hi)     = __floats2half2_rn(e2, e3);
            *(half2*)(e_hi + 8) = __floats2half2_rn(f2, f3);
        }
        __syncthreads();     // Es chunk cols complete (both wn halves)

        // ---- MMA2: O[16q x 128h per warp] += E[16 x 32] * Xchunk slice ----
        #pragma unroll
        for (int kst = 0; kst < 2; kst++) {
            uint32_t A0[4];
            ldsm4(a2r + (uint32_t)((i * TCHK + kst * 16) * 2), A0);
            #pragma unroll
            for (int nb = 0; nb < 8; nb++) {
                uint32_t Bv[4];
                ldsm4t(xcur + b2r + (uint32_t)((kst * 16 * XP + nb * 16) * 2), Bv);
                mma16816(&o[nb * 8],     A0, Bv);
                mma16816(&o[nb * 8 + 4], A0, Bv + 2);
            }
        }
    }

    // ---- reduce row sums across quad lanes (t-dim), publish per wn group ----
    {
        float v0 = rsum0, v1 = rsum1;
        v0 += __shfl_xor_sync(0xffffffffu, v0, 1);
        v0 += __shfl_xor_sync(0xffffffffu, v0, 2);
        v1 += __shfl_xor_sync(0xffffffffu, v1, 1);
        v1 += __shfl_xor_sync(0xffffffffu, v1, 2);
        if ((lane & 3) == 0) {
            rs[wn * 64 + m0 + r]     = v0;
            rs[wn * 64 + m0 + 8 + r] = v1;
        }
    }
    __syncthreads();
    if (tid < 64) inv[tid] = 1.0f / (rs[tid] + rs[64 + tid]);
    __syncthreads();

    // ---- write logits (scaled O fragments) ----
    {
        const int r0 = m0 + r;
        const float i0 = inv[r0], i1 = inv[r0 + 8];
        float* d0 = logits + (bL + l0 + r0) * HH;
        float* d1 = logits + (bL + l0 + r0 + 8) * HH;
        #pragma unroll
        for (int nf = 0; nf < 16; nf++) {
            const float* ov = &o[nf * 4];
            const int col = wn * 128 + nf * 8 + c2;
            *(float2*)(d0 + col) = make_float2(ov[0] * i0, ov[1] * i0);
            *(float2*)(d1 + col) = make_float2(ov[2] * i1, ov[3] * i1);
        }
    }

    // ---- write normalized attention from Es (single pass, coalesced) ----
    #pragma unroll
    for (int sub = 0; sub < 2; sub++) {
        const int rr = w * 8 + sub * 4 + (lane >> 3);
        const int cb = (lane & 7) * 4;
        const float iv = inv[rr];
        float* gd = att + (bL + l0 + rr) * TT;
        const __half* es = Es + rr * EP;
        #pragma unroll
        for (int j = 0; j < 32; j++) {
            const int col = cb + j * 32;
            float2 f0 = __half22float2(*(const half2*)(es + col));
            float2 f1 = __half22float2(*(const half2*)(es + col + 2));
            *(float4*)(gd + col) = make_float4(f0.x * iv, f0.y * iv, f1.x * iv, f1.y * iv);
        }
    }
}

extern "C" void kernel_launch(void* const* d_in, const int* in_sizes, int n_in,
                              void* d_out, int out_size)
{
    const float* X      = (const float*)d_in[0];
    const void*  labels = d_in[1];
    const float* table  = (const float*)d_in[2];
    float* logits = (float*)d_out;
    float* att    = logits + (size_t)BB * LL * HH;

    xconv<<<(BB * TT * HH) / (256 * 8), 256>>>(X);

    cudaFuncSetAttribute(pla_mma, cudaFuncAttributeMaxDynamicSharedMemorySize, SMEM_BYTES);
    pla_mma<<<BB * (LL / MQ), NTHR, SMEM_BYTES>>>(labels, table, logits, att);
}

// round 13
// speedup vs baseline: 1.0727x; 1.0727x over previous
#include <cuda_runtime.h>
#include <cuda_fp16.h>
#include <cstdint>

#define BB 16
#define TT 1024
#define HH 256
#define LL 2048
#define MQ 64
#define TCHK 64
#define NCHUNK 16
#define NTHR 256

// smem pitches (in halves)
#define QP 264
#define XP 264
#define EP 1048

// smem byte offsets
#define SO_RS4  0                      // float rs4[4][64]
#define SO_INV  1024                   // float inv[64]
#define SO_FLAG 1536
#define SO_Q    2048                   // 64*264*2 = 33792
#define SO_X    (2048 + 33792)         // 64*264*2 = 33792
#define SO_E    (2048 + 33792 + 33792) // 64*1048*2 = 134144
#define SMEM_BYTES (SO_E + MQ * EP * 2)   // 203776

__device__ __half g_Xh[(size_t)BB * TT * HH];

__device__ __forceinline__ uint32_t smem_u32(const void* p) {
    uint32_t a;
    asm("{ .reg .u64 t; cvta.to.shared.u64 t, %1; cvt.u32.u64 %0, t; }" : "=r"(a) : "l"(p));
    return a;
}
__device__ __forceinline__ void ldsm4(uint32_t a, uint32_t* r) {
    asm volatile("ldmatrix.sync.aligned.m8n8.x4.shared.b16 {%0,%1,%2,%3}, [%4];"
                 : "=r"(r[0]), "=r"(r[1]), "=r"(r[2]), "=r"(r[3]) : "r"(a));
}
__device__ __forceinline__ void ldsm4t(uint32_t a, uint32_t* r) {
    asm volatile("ldmatrix.sync.aligned.m8n8.x4.trans.shared.b16 {%0,%1,%2,%3}, [%4];"
                 : "=r"(r[0]), "=r"(r[1]), "=r"(r[2]), "=r"(r[3]) : "r"(a));
}
__device__ __forceinline__ void mma16816(float* d, const uint32_t* a, const uint32_t* b) {
    asm volatile("mma.sync.aligned.m16n8k16.row.col.f32.f16.f16.f32 "
                 "{%0,%1,%2,%3}, {%4,%5,%6,%7}, {%8,%9}, {%0,%1,%2,%3};"
                 : "+f"(d[0]), "+f"(d[1]), "+f"(d[2]), "+f"(d[3])
                 : "r"(a[0]), "r"(a[1]), "r"(a[2]), "r"(a[3]), "r"(b[0]), "r"(b[1]));
}

// ---------------- X f32 -> fp16 convert (one-time) ----------------
__global__ void __launch_bounds__(256)
xconv(const float* __restrict__ X)
{
    const size_t i = ((size_t)blockIdx.x * 256 + threadIdx.x) * 8;
    float4 a = *(const float4*)(X + i);
    float4 b = *(const float4*)(X + i + 4);
    half2 h[4] = { __floats2half2_rn(a.x, a.y), __floats2half2_rn(a.z, a.w),
                   __floats2half2_rn(b.x, b.y), __floats2half2_rn(b.z, b.w) };
    *(uint4*)(g_Xh + i) = *(uint4*)h;
}

// ------- main fused kernel: r3 structure (2M x 4N warps), fp16 X feed -------
__global__ void __launch_bounds__(NTHR, 1)
pla_mma(const void*  __restrict__ labels_raw, // (B,L) int32/int64
        const float* __restrict__ table,      // (C+1,H)
        float* __restrict__ logits,           // (B,L,H)
        float* __restrict__ att)              // (B,L,T)
{
    extern __shared__ char sm[];
    float*  rs4 = (float*)(sm + SO_RS4);
    float*  inv = (float*)(sm + SO_INV);
    __half* Qs  = (__half*)(sm + SO_Q);
    __half* Xs  = (__half*)(sm + SO_X);
    __half* Es  = (__half*)(sm + SO_E);
    const uint32_t smb = smem_u32(sm);
    const uint32_t Qb = smb + SO_Q, Xb_s = smb + SO_X, Eb = smb + SO_E;

    const int tid = threadIdx.x, lane = tid & 31, w = tid >> 5;
    const int wm = w & 1, wn = w >> 1;              // warp grid: 2(M) x 4(N)
    const int m0 = wm * 32;
    const int b = blockIdx.x >> 5, lt = blockIdx.x & 31, l0 = lt * MQ;
    const size_t bL = (size_t)b * LL;
    const __half* Xg = g_Xh + (size_t)b * TT * HH;

    rs4[tid] = 0.f;   // 4*64 floats

    // labels dtype detection (int64 LE, values < 2^31 => odd words zero)
    int* flag = (int*)(sm + SO_FLAG);
    if (tid == 0) {
        const int* li = (const int*)labels_raw;
        *flag = ((li[1] | li[3] | li[5] | li[7] | li[9] | li[11] | li[13] | li[15]) == 0);
    }
    __syncthreads();
    const bool is64 = (*flag != 0);

    // ---- gather Q (table[labels]) -> fp16 smem ----
    {
        const int q = tid >> 2, c0 = (tid & 3) * 4;
        const long long lidx = (long long)b * LL + l0 + q;
        const long long lab = is64 ? ((const long long*)labels_raw)[lidx]
                                   : (long long)((const int*)labels_raw)[lidx];
        const float* row = table + (size_t)lab * HH;
        #pragma unroll
        for (int j = 0; j < 16; j++) {
            const int col = c0 + j * 16;
            float4 v = *(const float4*)(row + col);
            *(half2*)(Qs + q * QP + col)     = __floats2half2_rn(v.x, v.y);
            *(half2*)(Qs + q * QP + col + 2) = __floats2half2_rn(v.z, v.w);
        }
    }

    // ---- prefetch X chunk 0 (fp16, one warp = one contiguous 512B row) ----
    // thread t: rows (t>>5) + p*8, cols (t&31)*8 halves, uint4 = 8 halves
    const int xrow = tid >> 5, xcol = (tid & 31) * 8;
    uint4 pr[8];
    #pragma unroll
    for (int p = 0; p < 8; p++)
        pr[p] = *(const uint4*)(Xg + (size_t)(xrow + p * 8) * HH + xcol);

    // per-thread running row sums (4 rows: mf{0,1} x {r, r+8})
    float rsum[4] = {0.f, 0.f, 0.f, 0.f};
    float o[64];
    #pragma unroll
    for (int i = 0; i < 64; i++) o[i] = 0.f;

    // ldmatrix base addresses (identical to the 203us r3 kernel)
    const uint32_t a1_0 = Qb + (uint32_t)(((m0 + (lane & 15)) * QP + ((lane >> 4) << 3)) * 2);
    const uint32_t b1_0 = Xb_s + (uint32_t)(((wn * 16 + (lane & 7) + ((lane >> 4) << 3)) * XP
                                             + ((lane >> 3) & 1) * 8) * 2);
    const uint32_t a2_0 = Eb + (uint32_t)(((m0 + (lane & 15)) * EP + ((lane >> 4) << 3)) * 2);
    const uint32_t b2_0 = Xb_s + (uint32_t)(((lane & 15) * XP + wn * 64 + ((lane >> 4) << 3)) * 2);

    const int r = lane >> 2, c2 = (lane & 3) * 2;

    for (int tc = 0; tc < NCHUNK; tc++) {
        // ---- store prefetched chunk -> Xs (direct uint4, no cvt) ----
        #pragma unroll
        for (int p = 0; p < 8; p++)
            *(uint4*)(Xs + (xrow + p * 8) * XP + xcol) = pr[p];
        __syncthreads();

        // ---- MMA1: S[64 x 64] = Q * Xchunk^T  (K = 256) ----
        float sa[4][4];
        #pragma unroll
        for (int i = 0; i < 4; i++)
            for (int j = 0; j < 4; j++) sa[i][j] = 0.f;
        #pragma unroll 4
        for (int k = 0; k < 16; k++) {
            uint32_t A0[4], A1[4], Bv[4];
            ldsm4(a1_0 + k * 32, A0);
            ldsm4(a1_0 + 16 * QP * 2 + k * 32, A1);
            ldsm4(b1_0 + k * 32, Bv);
            mma16816(sa[0], A0, Bv);
            mma16816(sa[1], A0, Bv + 2);
            mma16816(sa[2], A1, Bv);
            mma16816(sa[3], A1, Bv + 2);
        }

        // ---- prefetch next chunk (overlaps epilogue + MMA2) ----
        if (tc + 1 < NCHUNK) {
            const __half* src = Xg + (size_t)(tc + 1) * TCHK * HH;
            #pragma unroll
            for (int p = 0; p < 8; p++)
                pr[p] = *(const uint4*)(src + (size_t)(xrow + p * 8) * HH + xcol);
        }

        // ---- epilogue: e = exp(s) -> Es fp16, running row sums ----
        #pragma unroll
        for (int mf = 0; mf < 2; mf++) {
            #pragma unroll
            for (int nf = 0; nf < 2; nf++) {
                float* s = sa[mf * 2 + nf];
                const float e0 = __expf(s[0]), e1 = __expf(s[1]);
                const float e2 = __expf(s[2]), e3 = __expf(s[3]);
                rsum[mf * 2 + 0] += e0 + e1;
                rsum[mf * 2 + 1] += e2 + e3;
                const int row0 = m0 + mf * 16 + r;
                const int col = tc * TCHK + wn * 16 + nf * 8 + c2;
                *(half2*)(Es + row0 * EP + col)       = __floats2half2_rn(e0, e1);
                *(half2*)(Es + (row0 + 8) * EP + col) = __floats2half2_rn(e2, e3);
            }
        }
        __syncthreads();   // Es chunk visible to all warps

        // ---- MMA2: O[64 x 256] += E_chunk[64 x 64] * Xchunk[64 x 256] ----
        #pragma unroll
        for (int kst = 0; kst < 4; kst++) {
            uint32_t A0[4], A1[4], Bv[4][4];
            ldsm4(a2_0 + tc * 128 + kst * 32, A0);
            ldsm4(a2_0 + 16 * EP * 2 + tc * 128 + kst * 32, A1);
            #pragma unroll
            for (int nb = 0; nb < 4; nb++)
                ldsm4t(b2_0 + kst * 16 * XP * 2 + nb * 32, Bv[nb]);
            #pragma unroll
            for (int nf = 0; nf < 8; nf++) {
                const uint32_t* bp = &Bv[nf >> 1][(nf & 1) * 2];
                mma16816(&o[nf * 4],        A0, bp);
                mma16816(&o[32 + nf * 4],   A1, bp);
            }
        }
        __syncthreads();   // Xs free for next chunk
    }

    // ---- reduce row sums across quad lanes, publish, compute inverses ----
    #pragma unroll
    for (int mf = 0; mf < 2; mf++) {
        #pragma unroll
        for (int h = 0; h < 2; h++) {
            float v = rsum[mf * 2 + h];
            v += __shfl_xor_sync(0xffffffffu, v, 1);
            v += __shfl_xor_sync(0xffffffffu, v, 2);
            if ((lane & 3) == 0)
                rs4[wn * 64 + m0 + mf * 16 + h * 8 + r] = v;
        }
    }
    __syncthreads();
    if (tid < 64)
        inv[tid] = 1.0f / (rs4[tid] + rs4[64 + tid] + rs4[128 + tid] + rs4[192 + tid]);
    __syncthreads();

    // ---- write logits (scaled O fragments) ----
    #pragma unroll
    for (int mf = 0; mf < 2; mf++) {
        #pragma unroll
        for (int nf = 0; nf < 8; nf++) {
            const float* ov = &o[mf * 32 + nf * 4];
            const int r0 = m0 + mf * 16 + r;
            const int col = wn * 64 + nf * 8 + c2;
            const float i0 = inv[r0], i1 = inv[r0 + 8];
            float* d0 = logits + (bL + l0 + r0) * HH + col;
            float* d1 = logits + (bL + l0 + r0 + 8) * HH + col;
            *(float2*)d0 = make_float2(ov[0] * i0, ov[1] * i0);
            *(float2*)d1 = make_float2(ov[2] * i1, ov[3] * i1);
        }
    }

    // ---- write normalized attention from Es (single pass, coalesced) ----
    #pragma unroll
    for (int sub = 0; sub < 2; sub++) {
        const int rr = w * 8 + sub * 4 + (lane >> 3);
        const int cb = (lane & 7) * 4;
        const float iv = inv[rr];
        float* gd = att + (bL + l0 + rr) * TT;
        const __half* es = Es + rr * EP;
        #pragma unroll
        for (int j = 0; j < 32; j++) {
            const int col = cb + j * 32;
            float2 f0 = __half22float2(*(const half2*)(es + col));
            float2 f1 = __half22float2(*(const half2*)(es + col + 2));
            *(float4*)(gd + col) = make_float4(f0.x * iv, f0.y * iv, f1.x * iv, f1.y * iv);
        }
    }
}

extern "C" void kernel_launch(void* const* d_in, const int* in_sizes, int n_in,
                              void* d_out, int out_size)
{
    const float* X      = (const float*)d_in[0];
    const void*  labels = d_in[1];
    const float* table  = (const float*)d_in[2];
    float* logits = (float*)d_out;
    float* att    = logits + (size_t)BB * LL * HH;

    xconv<<<(BB * TT * HH) / (256 * 8), 256>>>(X);

    cudaFuncSetAttribute(pla_mma, cudaFuncAttributeMaxDynamicSharedMemorySize, SMEM_BYTES);
    pla_mma<<<BB * (LL / MQ), NTHR, SMEM_BYTES>>>(labels, table, logits, att);
}

// round 16
// speedup vs baseline: 1.1703x; 1.0910x over previous
#include <cuda_runtime.h>
#include <cuda_fp16.h>
#include <cstdint>

#define BB 16
#define TT 1024
#define HH 256
#define LL 2048
#define MQ 64
#define TCHK 64
#define NCHUNK 16
#define NTHR 512

// smem pitches (in halves)
#define QP 264
#define XP 264
#define EP 1048

// smem byte offsets (identical layout to the r10 kernel)
#define SO_RS4  0                      // float rs4[4][64]
#define SO_INV  1024                   // float inv[64]
#define SO_FLAG 1536
#define SO_Q    2048                   // 64*264*2 = 33792
#define SO_X    (2048 + 33792)         // 64*264*2 = 33792
#define SO_E    (2048 + 33792 + 33792) // 64*1048*2 = 134144
#define SMEM_BYTES (SO_E + MQ * EP * 2)   // 203776

__device__ __half g_Xh[(size_t)BB * TT * HH];

__device__ __forceinline__ uint32_t smem_u32(const void* p) {
    uint32_t a;
    asm("{ .reg .u64 t; cvta.to.shared.u64 t, %1; cvt.u32.u64 %0, t; }" : "=r"(a) : "l"(p));
    return a;
}
__device__ __forceinline__ void ldsm4(uint32_t a, uint32_t* r) {
    asm volatile("ldmatrix.sync.aligned.m8n8.x4.shared.b16 {%0,%1,%2,%3}, [%4];"
                 : "=r"(r[0]), "=r"(r[1]), "=r"(r[2]), "=r"(r[3]) : "r"(a));
}
__device__ __forceinline__ void ldsm4t(uint32_t a, uint32_t* r) {
    asm volatile("ldmatrix.sync.aligned.m8n8.x4.trans.shared.b16 {%0,%1,%2,%3}, [%4];"
                 : "=r"(r[0]), "=r"(r[1]), "=r"(r[2]), "=r"(r[3]) : "r"(a));
}
__device__ __forceinline__ void mma16816(float* d, const uint32_t* a, const uint32_t* b) {
    asm volatile("mma.sync.aligned.m16n8k16.row.col.f32.f16.f16.f32 "
                 "{%0,%1,%2,%3}, {%4,%5,%6,%7}, {%8,%9}, {%0,%1,%2,%3};"
                 : "+f"(d[0]), "+f"(d[1]), "+f"(d[2]), "+f"(d[3])
                 : "r"(a[0]), "r"(a[1]), "r"(a[2]), "r"(a[3]), "r"(b[0]), "r"(b[1]));
}

// ---------------- X f32 -> fp16 convert (one-time) ----------------
__global__ void __launch_bounds__(256)
xconv(const float* __restrict__ X)
{
    const size_t i = ((size_t)blockIdx.x * 256 + threadIdx.x) * 8;
    float4 a = *(const float4*)(X + i);
    float4 b = *(const float4*)(X + i + 4);
    half2 h[4] = { __floats2half2_rn(a.x, a.y), __floats2half2_rn(a.z, a.w),
                   __floats2half2_rn(b.x, b.y), __floats2half2_rn(b.z, b.w) };
    *(uint4*)(g_Xh + i) = *(uint4*)h;
}

// ---- main fused kernel: 512 threads, 4M x 4N warps (M=16), Es monolith ----
__global__ void __launch_bounds__(NTHR, 1)
pla_mma(const void*  __restrict__ labels_raw, // (B,L) int32/int64
        const float* __restrict__ table,      // (C+1,H)
        float* __restrict__ logits,           // (B,L,H)
        float* __restrict__ att)              // (B,L,T)
{
    extern __shared__ char sm[];
    float*  rs4 = (float*)(sm + SO_RS4);
    float*  inv = (float*)(sm + SO_INV);
    __half* Qs  = (__half*)(sm + SO_Q);
    __half* Xs  = (__half*)(sm + SO_X);
    __half* Es  = (__half*)(sm + SO_E);
    const uint32_t smb = smem_u32(sm);
    const uint32_t Qb = smb + SO_Q, Xb_s = smb + SO_X, Eb = smb + SO_E;

    const int tid = threadIdx.x, lane = tid & 31, w = tid >> 5;
    const int wm = w & 3, wn = w >> 2;       // 4(M) x 4(N)
    const int m0 = wm * 16;
    const int b = blockIdx.x >> 5, lt = blockIdx.x & 31, l0 = lt * MQ;
    const size_t bL = (size_t)b * LL;
    const __half* Xg = g_Xh + (size_t)b * TT * HH;

    if (tid < 256) rs4[tid] = 0.f;

    // labels dtype detection (int64 LE, values < 2^31 => odd words zero)
    int* flag = (int*)(sm + SO_FLAG);
    if (tid == 0) {
        const int* li = (const int*)labels_raw;
        *flag = ((li[1] | li[3] | li[5] | li[7] | li[9] | li[11] | li[13] | li[15]) == 0);
    }
    __syncthreads();
    const bool is64 = (*flag != 0);

    // ---- gather Q (table[labels]) -> fp16 smem ----
    {
        const int q = tid >> 3, c0 = (tid & 7) * 4;
        const long long lidx = (long long)b * LL + l0 + q;
        const long long lab = is64 ? ((const long long*)labels_raw)[lidx]
                                   : (long long)((const int*)labels_raw)[lidx];
        const float* row = table + (size_t)lab * HH;
        #pragma unroll
        for (int j = 0; j < 8; j++) {
            const int col = c0 + j * 32;
            float4 v = *(const float4*)(row + col);
            *(half2*)(Qs + q * QP + col)     = __floats2half2_rn(v.x, v.y);
            *(half2*)(Qs + q * QP + col + 2) = __floats2half2_rn(v.z, v.w);
        }
    }

    // ---- prefetch X chunk 0 (fp16): thread -> row tid>>3, 64B contiguous ----
    const int xrow = tid >> 3, xcol = (tid & 7) * 32;
    uint4 pr[4];
    #pragma unroll
    for (int p = 0; p < 4; p++)
        pr[p] = *(const uint4*)(Xg + (size_t)xrow * HH + xcol + p * 8);

    float rsum0 = 0.f, rsum1 = 0.f;   // rows m0+r, m0+8+r (partial over wn t-slice)
    float o[32];
    #pragma unroll
    for (int i = 0; i < 32; i++) o[i] = 0.f;

    // ldmatrix base addresses (proven r5/r10 formulas)
    const uint32_t a1_0 = Qb + (uint32_t)(((m0 + (lane & 15)) * QP + ((lane >> 4) << 3)) * 2);
    const uint32_t b1_0 = Xb_s + (uint32_t)(((wn * 16 + (lane & 7) + ((lane >> 4) << 3)) * XP
                                             + ((lane >> 3) & 1) * 8) * 2);
    const uint32_t a2_0 = Eb + (uint32_t)(((m0 + (lane & 15)) * EP + ((lane >> 4) << 3)) * 2);
    const uint32_t b2_0 = Xb_s + (uint32_t)(((lane & 15) * XP + wn * 64 + ((lane >> 4) << 3)) * 2);

    const int r = lane >> 2, c2 = (lane & 3) * 2;

    for (int tc = 0; tc < NCHUNK; tc++) {
        // ---- store prefetched chunk -> Xs (direct uint4, no cvt) ----
        #pragma unroll
        for (int p = 0; p < 4; p++)
            *(uint4*)(Xs + xrow * XP + xcol + p * 8) = pr[p];
        __syncthreads();

        // ---- MMA1: S[16q x 16t per warp] = Q * Xchunk^T (K = 256) ----
        float sa0[4] = {0.f, 0.f, 0.f, 0.f};
        float sa1[4] = {0.f, 0.f, 0.f, 0.f};
        #pragma unroll 4
        for (int k = 0; k < 16; k++) {
            uint32_t A0[4], Bv[4];
            ldsm4(a1_0 + k * 32, A0);
            ldsm4(b1_0 + k * 32, Bv);
            mma16816(sa0, A0, Bv);
            mma16816(sa1, A0, Bv + 2);
        }

        // ---- prefetch next chunk (overlaps epilogue + MMA2) ----
        if (tc + 1 < NCHUNK) {
            const __half* src = Xg + (size_t)((tc + 1) * TCHK + xrow) * HH + xcol;
            #pragma unroll
            for (int p = 0; p < 4; p++)
                pr[p] = *(const uint4*)(src + p * 8);
        }

        // ---- epilogue: e = exp(s) -> Es monolith + running row sums ----
        {
            const float e0 = __expf(sa0[0]), e1 = __expf(sa0[1]);
            const float e2 = __expf(sa0[2]), e3 = __expf(sa0[3]);
            const float f0 = __expf(sa1[0]), f1 = __expf(sa1[1]);
            const float f2 = __expf(sa1[2]), f3 = __expf(sa1[3]);
            rsum0 += e0 + e1 + f0 + f1;
            rsum1 += e2 + e3 + f2 + f3;
            const int col = tc * TCHK + wn * 16 + c2;
            __half* e_lo = Es + (m0 + r) * EP + col;
            __half* e_hi = e_lo + 8 * EP;
            *(half2*)(e_lo)     = __floats2half2_rn(e0, e1);
            *(half2*)(e_lo + 8) = __floats2half2_rn(f0, f1);
            *(half2*)(e_hi)     = __floats2half2_rn(e2, e3);
            *(half2*)(e_hi + 8) = __floats2half2_rn(f2, f3);
        }
        __syncthreads();   // Es chunk visible to all warps

        // ---- MMA2: O[16q x 64h per warp] += E[16 x 64] * Xchunk slice ----
        #pragma unroll
        for (int kst = 0; kst < 4; kst++) {
            uint32_t A0[4], Bv[4][4];
            ldsm4(a2_0 + tc * 128 + kst * 32, A0);
            #pragma unroll
            for (int nb = 0; nb < 4; nb++)
                ldsm4t(b2_0 + kst * 16 * XP * 2 + nb * 32, Bv[nb]);
            #pragma unroll
            for (int nf = 0; nf < 8; nf++)
                mma16816(&o[nf * 4], A0, &Bv[nf >> 1][(nf & 1) * 2]);
        }
        __syncthreads();   // Xs free for next chunk
    }

    // ---- reduce row sums across quad lanes, publish, compute inverses ----
    {
        float v0 = rsum0, v1 = rsum1;
        v0 += __shfl_xor_sync(0xffffffffu, v0, 1);
        v0 += __shfl_xor_sync(0xffffffffu, v0, 2);
        v1 += __shfl_xor_sync(0xffffffffu, v1, 1);
        v1 += __shfl_xor_sync(0xffffffffu, v1, 2);
        if ((lane & 3) == 0) {
            rs4[wn * 64 + m0 + r]     = v0;
            rs4[wn * 64 + m0 + 8 + r] = v1;
        }
    }
    __syncthreads();
    if (tid < 64)
        inv[tid] = 1.0f / (rs4[tid] + rs4[64 + tid] + rs4[128 + tid] + rs4[192 + tid]);
    __syncthreads();

    // ---- write logits (scaled O fragments) ----
    {
        const int r0 = m0 + r;
        const float i0 = inv[r0], i1 = inv[r0 + 8];
        float* d0 = logits + (bL + l0 + r0) * HH;
        float* d1 = logits + (bL + l0 + r0 + 8) * HH;
        #pragma unroll
        for (int nf = 0; nf < 8; nf++) {
            const float* ov = &o[nf * 4];
            const int col = wn * 64 + nf * 8 + c2;
            *(float2*)(d0 + col) = make_float2(ov[0] * i0, ov[1] * i0);
            *(float2*)(d1 + col) = make_float2(ov[2] * i1, ov[3] * i1);
        }
    }

    // ---- write normalized attention from Es (single pass, coalesced) ----
    {
        const int rr = w * 4 + (lane >> 3);       // 16 warps x 4 rows
        const int cb = (lane & 7) * 4;
        const float iv = inv[rr];
        float* gd = att + (bL + l0 + rr) * TT;
        const __half* es = Es + rr * EP;
        #pragma unroll
        for (int j = 0; j < 32; j++) {
            const int col = cb + j * 32;
            float2 f0 = __half22float2(*(const half2*)(es + col));
            float2 f1 = __half22float2(*(const half2*)(es + col + 2));
            *(float4*)(gd + col) = make_float4(f0.x * iv, f0.y * iv, f1.x * iv, f1.y * iv);
        }
    }
}

extern "C" void kernel_launch(void* const* d_in, const int* in_sizes, int n_in,
                              void* d_out, int out_size)
{
    const float* X      = (const float*)d_in[0];
    const void*  labels = d_in[1];
    const float* table  = (const float*)d_in[2];
    float* logits = (float*)d_out;
    float* att    = logits + (size_t)BB * LL * HH;

    xconv<<<(BB * TT * HH) / (256 * 8), 256>>>(X);

    cudaFuncSetAttribute(pla_mma, cudaFuncAttributeMaxDynamicSharedMemorySize, SMEM_BYTES);
    pla_mma<<<BB * (LL / MQ), NTHR, SMEM_BYTES>>>(labels, table, logits, att);
}